// round 1
// baseline (speedup 1.0000x reference)
#include <cuda_runtime.h>
#include <math.h>

// Problem constants
#define B_    4
#define L_    4096
#define H_    1024
#define LC_   1024      // compressed length per batch (4096/4)
#define KSEL_ 512
#define WIN_  256
#define NW_   16        // windows that survive truncation to L
#define SCALE_ 0.125f   // 1/sqrt(1024/16)

typedef long long ll;

// ---------------- scratch (device globals; no allocation allowed) -------------
__device__ float g_Q[(size_t)B_ * L_ * H_];
__device__ float g_Kbuf[(size_t)B_ * L_ * H_];
__device__ float g_Vbuf[(size_t)B_ * L_ * H_];
__device__ float g_cmp[(size_t)B_ * LC_ * H_];
__device__ float g_Qc[(size_t)B_ * LC_ * H_];
__device__ float g_Kc[(size_t)B_ * LC_ * H_];
__device__ float g_Vc[(size_t)B_ * LC_ * H_];
__device__ float g_S[(size_t)B_ * LC_ * LC_];          // reused for all score mats
__device__ float g_comp_out[(size_t)B_ * LC_ * H_];
__device__ float g_Qs[(size_t)B_ * KSEL_ * H_];
__device__ float g_Ks[(size_t)B_ * KSEL_ * H_];
__device__ float g_Vs[(size_t)B_ * KSEL_ * H_];
__device__ float g_sel_out[(size_t)B_ * KSEL_ * H_];
__device__ float g_win_out[(size_t)B_ * L_ * H_];
__device__ float g_comb[(size_t)B_ * L_ * 3 * H_];
__device__ float g_pre[(size_t)B_ * L_ * H_];
__device__ float g_gates[(size_t)B_ * L_ * 3];
__device__ float g_scores[(size_t)B_ * L_];
__device__ int   g_idx[B_ * KSEL_];

// ---------------- generic 128x128x8 SGEMM (batched, optional B^T) -------------
// C[z] = alpha * A[z] (x) B[z] + bias     (bias may be null)
// A: M x K row-major (row stride K). B: K x N row-major if !TRANS_B,
// else N x K row-major (i.e. C = A * B^T). C: M x N row-major.
// Per-batch base: ptr + (z/innerCnt)*strideOuter + (z%innerCnt)*strideInner.
// REQUIRES: M%128==0, N%128==0, K%8==0 (all call sites satisfy this).
template <bool TRANS_B>
__global__ void __launch_bounds__(256)
gemm_kernel(const float* __restrict__ A, const float* __restrict__ Bm,
            const float* __restrict__ bias, float* __restrict__ C,
            int M, int N, int K, float alpha,
            ll saO, ll saI, int innerCnt,
            ll sbO, ll sbI, ll sC)
{
    const int z = blockIdx.z;
    const float* Ab = A + (ll)(z / innerCnt) * saO + (ll)(z % innerCnt) * saI;
    const float* Bb = Bm + (ll)(z / innerCnt) * sbO + (ll)(z % innerCnt) * sbI;
    float* Cb = C + (ll)z * sC;

    __shared__ float As[8][128];
    __shared__ float Bs[8][128];

    const int tid = threadIdx.x;
    const int tx = tid & 15;        // 0..15 -> 8 cols each
    const int ty = tid >> 4;        // 0..15 -> 8 rows each
    const int rowBase = blockIdx.y * 128;
    const int colBase = blockIdx.x * 128;

    float acc[8][8];
#pragma unroll
    for (int i = 0; i < 8; i++)
#pragma unroll
        for (int j = 0; j < 8; j++) acc[i][j] = 0.f;

    const int aRow = tid >> 1;          // 0..127
    const int aCol = (tid & 1) << 2;    // 0 or 4

    for (int k0 = 0; k0 < K; k0 += 8) {
        float4 av = *(const float4*)(Ab + (ll)(rowBase + aRow) * K + k0 + aCol);
        As[aCol + 0][aRow] = av.x; As[aCol + 1][aRow] = av.y;
        As[aCol + 2][aRow] = av.z; As[aCol + 3][aRow] = av.w;
        if (!TRANS_B) {
            const int bRow = tid >> 5;            // 0..7
            const int bCol = (tid & 31) << 2;     // 0..124
            float4 bv = *(const float4*)(Bb + (ll)(k0 + bRow) * N + colBase + bCol);
            Bs[bRow][bCol + 0] = bv.x; Bs[bRow][bCol + 1] = bv.y;
            Bs[bRow][bCol + 2] = bv.z; Bs[bRow][bCol + 3] = bv.w;
        } else {
            float4 bv = *(const float4*)(Bb + (ll)(colBase + aRow) * K + k0 + aCol);
            Bs[aCol + 0][aRow] = bv.x; Bs[aCol + 1][aRow] = bv.y;
            Bs[aCol + 2][aRow] = bv.z; Bs[aCol + 3][aRow] = bv.w;
        }
        __syncthreads();
#pragma unroll
        for (int kk = 0; kk < 8; kk++) {
            float4 ra0 = *(const float4*)&As[kk][ty * 8];
            float4 ra1 = *(const float4*)&As[kk][ty * 8 + 4];
            float4 rb0 = *(const float4*)&Bs[kk][tx * 8];
            float4 rb1 = *(const float4*)&Bs[kk][tx * 8 + 4];
            float ra[8] = {ra0.x, ra0.y, ra0.z, ra0.w, ra1.x, ra1.y, ra1.z, ra1.w};
            float rb[8] = {rb0.x, rb0.y, rb0.z, rb0.w, rb1.x, rb1.y, rb1.z, rb1.w};
#pragma unroll
            for (int i = 0; i < 8; i++)
#pragma unroll
                for (int j = 0; j < 8; j++) acc[i][j] += ra[i] * rb[j];
        }
        __syncthreads();
    }

#pragma unroll
    for (int i = 0; i < 8; i++) {
        const int row = rowBase + ty * 8 + i;
        const int col = colBase + tx * 8;
        float4 b0 = make_float4(0.f, 0.f, 0.f, 0.f), b1 = b0;
        if (bias) {
            b0 = *(const float4*)&bias[col];
            b1 = *(const float4*)&bias[col + 4];
        }
        float4 o0 = make_float4(alpha * acc[i][0] + b0.x, alpha * acc[i][1] + b0.y,
                                alpha * acc[i][2] + b0.z, alpha * acc[i][3] + b0.w);
        float4 o1 = make_float4(alpha * acc[i][4] + b1.x, alpha * acc[i][5] + b1.y,
                                alpha * acc[i][6] + b1.z, alpha * acc[i][7] + b1.w);
        *(float4*)(Cb + (ll)row * N + col) = o0;
        *(float4*)(Cb + (ll)row * N + col + 4) = o1;
    }
}

// ---------------- gates (sigmoid + normalize) and selection scores ------------
__global__ void gates_scores_kernel(const float* __restrict__ x,
                                    const float* __restrict__ Wg, const float* __restrict__ bg,
                                    const float* __restrict__ Ws, const float* __restrict__ bs,
                                    float* __restrict__ gates, float* __restrict__ scores)
{
    const int row = blockIdx.x * (blockDim.x >> 5) + (threadIdx.x >> 5);
    const int lane = threadIdx.x & 31;
    if (row >= B_ * L_) return;
    const float* xr = x + (ll)row * H_;
    float a0 = 0.f, a1 = 0.f, a2 = 0.f, a3 = 0.f;
    for (int k = lane; k < H_; k += 32) {
        const float xv = xr[k];
        a0 += xv * Wg[k * 3 + 0];
        a1 += xv * Wg[k * 3 + 1];
        a2 += xv * Wg[k * 3 + 2];
        a3 += xv * Ws[k];
    }
#pragma unroll
    for (int o = 16; o > 0; o >>= 1) {
        a0 += __shfl_down_sync(0xffffffffu, a0, o);
        a1 += __shfl_down_sync(0xffffffffu, a1, o);
        a2 += __shfl_down_sync(0xffffffffu, a2, o);
        a3 += __shfl_down_sync(0xffffffffu, a3, o);
    }
    if (lane == 0) {
        float s0 = 1.f / (1.f + expf(-(a0 + bg[0])));
        float s1 = 1.f / (1.f + expf(-(a1 + bg[1])));
        float s2 = 1.f / (1.f + expf(-(a2 + bg[2])));
        float inv = 1.f / (s0 + s1 + s2 + 1e-6f);
        gates[row * 3 + 0] = s0 * inv;
        gates[row * 3 + 1] = s1 * inv;
        gates[row * 3 + 2] = s2 * inv;
        scores[row] = a3 + bs[0];
    }
}

// ---------------- top-512 per batch: bitonic sort 4096, then sort indices ----
__global__ void topk_kernel(const float* __restrict__ scores, int* __restrict__ idx_out)
{
    __shared__ float sv[L_];
    __shared__ int   si[L_];
    __shared__ int   top[KSEL_];
    const int b = blockIdx.x;
    const float* s = scores + (ll)b * L_;
    for (int i = threadIdx.x; i < L_; i += blockDim.x) { sv[i] = s[i]; si[i] = i; }
    __syncthreads();
    for (int k = 2; k <= L_; k <<= 1)
        for (int j = k >> 1; j > 0; j >>= 1) {
            for (int i = threadIdx.x; i < L_; i += blockDim.x) {
                const int ixj = i ^ j;
                if (ixj > i) {
                    const bool desc = ((i & k) == 0);
                    const float a = sv[i], c = sv[ixj];
                    const bool sw = desc ? (a < c) : (a > c);
                    if (sw) {
                        sv[i] = c; sv[ixj] = a;
                        const int t = si[i]; si[i] = si[ixj]; si[ixj] = t;
                    }
                }
            }
            __syncthreads();
        }
    for (int i = threadIdx.x; i < KSEL_; i += blockDim.x) top[i] = si[i];
    __syncthreads();
    for (int k = 2; k <= KSEL_; k <<= 1)
        for (int j = k >> 1; j > 0; j >>= 1) {
            for (int i = threadIdx.x; i < KSEL_; i += blockDim.x) {
                const int ixj = i ^ j;
                if (ixj > i) {
                    const bool asc = ((i & k) == 0);
                    const int a = top[i], c = top[ixj];
                    const bool sw = asc ? (a > c) : (a < c);
                    if (sw) { top[i] = c; top[ixj] = a; }
                }
            }
            __syncthreads();
        }
    for (int i = threadIdx.x; i < KSEL_; i += blockDim.x) idx_out[b * KSEL_ + i] = top[i];
}

// ---------------- gather selected token QKV rows ------------------------------
__global__ void gather_kernel(const float* __restrict__ Q, const float* __restrict__ K,
                              const float* __restrict__ V, const int* __restrict__ idx,
                              float* __restrict__ Qs, float* __restrict__ Ks, float* __restrict__ Vs)
{
    const int b = blockIdx.y, r = blockIdx.x;
    const int src = idx[b * KSEL_ + r];
    const ll so = ((ll)b * L_ + src) * H_;
    const ll dst = ((ll)b * KSEL_ + r) * H_;
    for (int i = threadIdx.x; i < H_; i += blockDim.x) {
        Qs[dst + i] = Q[so + i];
        Ks[dst + i] = K[so + i];
        Vs[dst + i] = V[so + i];
    }
}

// ---------------- row softmax --------------------------------------------------
__global__ void softmax_kernel(float* __restrict__ S, int n)
{
    const ll row = blockIdx.x;
    float* s = S + row * (ll)n;
    const int tid = threadIdx.x;
    __shared__ float red[32];
    __shared__ float bc;

    float m = -1e30f;
    for (int i = tid; i < n; i += blockDim.x) m = fmaxf(m, s[i]);
#pragma unroll
    for (int o = 16; o > 0; o >>= 1) m = fmaxf(m, __shfl_xor_sync(0xffffffffu, m, o));
    if ((tid & 31) == 0) red[tid >> 5] = m;
    __syncthreads();
    if (tid == 0) {
        float mm = -1e30f;
        for (int i = 0; i < (int)(blockDim.x >> 5); i++) mm = fmaxf(mm, red[i]);
        bc = mm;
    }
    __syncthreads();
    m = bc;
    __syncthreads();

    float sum = 0.f;
    for (int i = tid; i < n; i += blockDim.x) {
        const float e = expf(s[i] - m);
        s[i] = e;
        sum += e;
    }
#pragma unroll
    for (int o = 16; o > 0; o >>= 1) sum += __shfl_xor_sync(0xffffffffu, sum, o);
    if ((tid & 31) == 0) red[tid >> 5] = sum;
    __syncthreads();
    if (tid == 0) {
        float ss = 0.f;
        for (int i = 0; i < (int)(blockDim.x >> 5); i++) ss += red[i];
        bc = 1.f / ss;
    }
    __syncthreads();
    const float inv = bc;
    for (int i = tid; i < n; i += blockDim.x) s[i] *= inv;
}

// ---------------- assemble gated combined [comp | sel | win] ------------------
__global__ void assemble_kernel(const float* __restrict__ comp_out, const float* __restrict__ sel_out,
                                const float* __restrict__ win_out, const float* __restrict__ gates,
                                float* __restrict__ comb)
{
    const ll t = blockIdx.x;            // 0..16383
    const int b = (int)(t >> 12), l = (int)(t & 4095);
    const float g0 = gates[t * 3 + 0], g1 = gates[t * 3 + 1], g2 = gates[t * 3 + 2];
    float* c = comb + t * (ll)(3 * H_);
    const float* co = comp_out + ((ll)b * LC_ + l) * H_;
    const float* so = sel_out + ((ll)b * KSEL_ + l) * H_;
    const float* wo = win_out + t * (ll)H_;
    const bool hasC = (l < LC_), hasS = (l < KSEL_);
    for (int i = threadIdx.x; i < H_; i += blockDim.x) {
        c[i]            = hasC ? co[i] * g0 : 0.f;
        c[H_ + i]       = hasS ? so[i] * g1 : 0.f;
        c[2 * H_ + i]   = wo[i] * g2;
    }
}

// ---------------- residual + layernorm ----------------------------------------
__global__ void final_ln_kernel(const float* __restrict__ pre, const float* __restrict__ x,
                                float* __restrict__ out)
{
    const ll row = blockIdx.x;
    const float* p = pre + row * (ll)H_;
    const float* xr = x + row * (ll)H_;
    float* o = out + row * (ll)H_;
    const int tid = threadIdx.x;
    __shared__ float buf[H_];
    __shared__ float red[64];
    __shared__ float stats[2];

    float s = 0.f, ss = 0.f;
    for (int i = tid; i < H_; i += blockDim.x) {
        const float v = 0.5f * (p[i] + xr[i]);
        buf[i] = v;
        s += v;
        ss += v * v;
    }
#pragma unroll
    for (int o2 = 16; o2 > 0; o2 >>= 1) {
        s  += __shfl_xor_sync(0xffffffffu, s, o2);
        ss += __shfl_xor_sync(0xffffffffu, ss, o2);
    }
    if ((tid & 31) == 0) { red[tid >> 5] = s; red[32 + (tid >> 5)] = ss; }
    __syncthreads();
    if (tid == 0) {
        float ts = 0.f, tss = 0.f;
        for (int i = 0; i < (int)(blockDim.x >> 5); i++) { ts += red[i]; tss += red[32 + i]; }
        const float mean = ts / (float)H_;
        const float var = tss / (float)H_ - mean * mean;
        stats[0] = mean;
        stats[1] = rsqrtf(var + 1e-6f);
    }
    __syncthreads();
    const float mean = stats[0], inv = stats[1];
    for (int i = tid; i < H_; i += blockDim.x) o[i] = (buf[i] - mean) * inv;
}

// ------------------------------- launcher --------------------------------------
extern "C" void kernel_launch(void* const* d_in, const int* in_sizes, int n_in,
                              void* d_out, int out_size)
{
    const float* x  = (const float*)d_in[0];
    const float* Wq = (const float*)d_in[1];
    const float* bq = (const float*)d_in[2];
    const float* Wk = (const float*)d_in[3];
    const float* bk = (const float*)d_in[4];
    const float* Wv = (const float*)d_in[5];
    const float* bv = (const float*)d_in[6];
    const float* Wo = (const float*)d_in[7];
    const float* bo = (const float*)d_in[8];
    const float* Wg = (const float*)d_in[9];
    const float* bg = (const float*)d_in[10];
    const float* Wc = (const float*)d_in[11];
    const float* bc = (const float*)d_in[12];
    const float* Ws = (const float*)d_in[13];
    const float* bs = (const float*)d_in[14];
    float* out = (float*)d_out;

    float *Q, *K, *V, *cmp, *Qc, *Kc, *Vc, *S, *comp_out;
    float *Qs, *Ks, *Vs, *sel_out, *win_out, *comb, *pre, *gates, *scores;
    int* idx;
    cudaGetSymbolAddress((void**)&Q, g_Q);
    cudaGetSymbolAddress((void**)&K, g_Kbuf);
    cudaGetSymbolAddress((void**)&V, g_Vbuf);
    cudaGetSymbolAddress((void**)&cmp, g_cmp);
    cudaGetSymbolAddress((void**)&Qc, g_Qc);
    cudaGetSymbolAddress((void**)&Kc, g_Kc);
    cudaGetSymbolAddress((void**)&Vc, g_Vc);
    cudaGetSymbolAddress((void**)&S, g_S);
    cudaGetSymbolAddress((void**)&comp_out, g_comp_out);
    cudaGetSymbolAddress((void**)&Qs, g_Qs);
    cudaGetSymbolAddress((void**)&Ks, g_Ks);
    cudaGetSymbolAddress((void**)&Vs, g_Vs);
    cudaGetSymbolAddress((void**)&sel_out, g_sel_out);
    cudaGetSymbolAddress((void**)&win_out, g_win_out);
    cudaGetSymbolAddress((void**)&comb, g_comb);
    cudaGetSymbolAddress((void**)&pre, g_pre);
    cudaGetSymbolAddress((void**)&gates, g_gates);
    cudaGetSymbolAddress((void**)&scores, g_scores);
    cudaGetSymbolAddress((void**)&idx, g_idx);

    const int MT = B_ * L_;   // 16384 total tokens

    // gates + selection scores (stay fp32 forever: selection boundary safety)
    gates_scores_kernel<<<MT / 8, 256>>>(x, Wg, bg, Ws, bs, gates, scores);

    // full-sequence QKV (shared by selected + window branches)
    {
        dim3 g(H_ / 128, MT / 128, 1);
        gemm_kernel<false><<<g, 256>>>(x, Wq, bq, Q, MT, H_, H_, 1.f, 0, 0, 1, 0, 0, 0);
        gemm_kernel<false><<<g, 256>>>(x, Wk, bk, K, MT, H_, H_, 1.f, 0, 0, 1, 0, 0, 0);
        gemm_kernel<false><<<g, 256>>>(x, Wv, bv, V, MT, H_, H_, 1.f, 0, 0, 1, 0, 0, 0);
    }

    // compressed tokens: blocks is a pure reshape of x -> direct GEMM, K=4096
    {
        dim3 g(H_ / 128, (B_ * LC_) / 128, 1);
        gemm_kernel<false><<<g, 256>>>(x, Wc, bc, cmp, B_ * LC_, H_, 4 * H_, 1.f, 0, 0, 1, 0, 0, 0);
        gemm_kernel<false><<<g, 256>>>(cmp, Wq, bq, Qc, B_ * LC_, H_, H_, 1.f, 0, 0, 1, 0, 0, 0);
        gemm_kernel<false><<<g, 256>>>(cmp, Wk, bk, Kc, B_ * LC_, H_, H_, 1.f, 0, 0, 1, 0, 0, 0);
        gemm_kernel<false><<<g, 256>>>(cmp, Wv, bv, Vc, B_ * LC_, H_, H_, 1.f, 0, 0, 1, 0, 0, 0);
    }

    // selection
    topk_kernel<<<B_, 512>>>(scores, idx);
    gather_kernel<<<dim3(KSEL_, B_), 256>>>(Q, K, V, idx, Qs, Ks, Vs);

    // ---- compressed-branch attention (B batches of 1024x1024, d=1024) ----
    gemm_kernel<true><<<dim3(LC_ / 128, LC_ / 128, B_), 256>>>(
        Qc, Kc, nullptr, S, LC_, LC_, H_, SCALE_,
        (ll)LC_ * H_, 0, 1, (ll)LC_ * H_, 0, (ll)LC_ * LC_);
    softmax_kernel<<<B_ * LC_, 256>>>(S, LC_);
    gemm_kernel<false><<<dim3(H_ / 128, LC_ / 128, B_), 256>>>(
        S, Vc, nullptr, comp_out, LC_, H_, LC_, 1.f,
        (ll)LC_ * LC_, 0, 1, (ll)LC_ * H_, 0, (ll)LC_ * H_);

    // ---- selected-branch attention (B batches of 512x512, d=1024) ----
    gemm_kernel<true><<<dim3(KSEL_ / 128, KSEL_ / 128, B_), 256>>>(
        Qs, Ks, nullptr, S, KSEL_, KSEL_, H_, SCALE_,
        (ll)KSEL_ * H_, 0, 1, (ll)KSEL_ * H_, 0, (ll)KSEL_ * KSEL_);
    softmax_kernel<<<B_ * KSEL_, 256>>>(S, KSEL_);
    gemm_kernel<false><<<dim3(H_ / 128, KSEL_ / 128, B_), 256>>>(
        S, Vs, nullptr, sel_out, KSEL_, H_, KSEL_, 1.f,
        (ll)KSEL_ * KSEL_, 0, 1, (ll)KSEL_ * H_, 0, (ll)KSEL_ * H_);

    // ---- window-branch attention (B*16 windows of 256x256, d=1024) ----
    // window w rows are the CONTIGUOUS Q/K/V rows starting at 128*w.
    gemm_kernel<true><<<dim3(WIN_ / 128, WIN_ / 128, B_ * NW_), 256>>>(
        Q, K, nullptr, S, WIN_, WIN_, H_, SCALE_,
        (ll)L_ * H_, (ll)128 * H_, NW_,
        (ll)L_ * H_, (ll)128 * H_, (ll)WIN_ * WIN_);
    softmax_kernel<<<B_ * NW_ * WIN_, 256>>>(S, WIN_);
    gemm_kernel<false><<<dim3(H_ / 128, WIN_ / 128, B_ * NW_), 256>>>(
        S, V, nullptr, win_out, WIN_, H_, WIN_, 1.f,
        (ll)NW_ * WIN_ * WIN_, (ll)WIN_ * WIN_, NW_,
        (ll)L_ * H_, (ll)128 * H_, (ll)WIN_ * H_);

    // gated concat, output projection, residual + layernorm
    assemble_kernel<<<MT, 256>>>(comp_out, sel_out, win_out, gates, comb);
    gemm_kernel<false><<<dim3(H_ / 128, MT / 128, 1), 256>>>(
        comb, Wo, bo, pre, MT, H_, 3 * H_, 1.f, 0, 0, 1, 0, 0, 0);
    final_ln_kernel<<<MT, 256>>>(pre, x, out);
}

// round 2
// speedup vs baseline: 2.6831x; 2.6831x over previous
#include <cuda_runtime.h>
#include <math.h>
#include <stdint.h>

// Problem constants
#define B_    4
#define L_    4096
#define H_    1024
#define LC_   1024
#define KSEL_ 512
#define WIN_  256
#define NW_   16
#define SCALE_ 0.125f

typedef long long ll;

// ---------------- scratch -----------------------------------------------------
__device__ float g_Q[(size_t)B_ * L_ * H_];
__device__ float g_Kbuf[(size_t)B_ * L_ * H_];
__device__ float g_Vbuf[(size_t)B_ * L_ * H_];
__device__ float g_cmp[(size_t)B_ * LC_ * H_];
__device__ float g_Qc[(size_t)B_ * LC_ * H_];
__device__ float g_Kc[(size_t)B_ * LC_ * H_];
__device__ float g_Vc[(size_t)B_ * LC_ * H_];
__device__ float g_S[(size_t)B_ * LC_ * LC_];
__device__ float g_comp_out[(size_t)B_ * LC_ * H_];
__device__ float g_Qs[(size_t)B_ * KSEL_ * H_];
__device__ float g_Ks[(size_t)B_ * KSEL_ * H_];
__device__ float g_Vs[(size_t)B_ * KSEL_ * H_];
__device__ float g_sel_out[(size_t)B_ * KSEL_ * H_];
__device__ float g_win_out[(size_t)B_ * L_ * H_];
__device__ float g_comb[(size_t)B_ * L_ * 3 * H_];
__device__ float g_pre[(size_t)B_ * L_ * H_];
__device__ float g_gates[(size_t)B_ * L_ * 3];
__device__ float g_scores[(size_t)B_ * L_];
__device__ int   g_idx[B_ * KSEL_];

// ---------------- tf32 helpers ------------------------------------------------
__device__ __forceinline__ float f2tf32(float x) {
    uint32_t u;
    asm("cvt.rna.tf32.f32 %0, %1;" : "=r"(u) : "f"(x));
    return __uint_as_float(u);
}

__device__ __forceinline__ void mma_tf32(float& c0, float& c1, float& c2, float& c3,
                                         uint32_t a0, uint32_t a1, uint32_t a2, uint32_t a3,
                                         uint32_t b0, uint32_t b1) {
    asm volatile(
        "mma.sync.aligned.m16n8k8.row.col.f32.tf32.tf32.f32 "
        "{%0,%1,%2,%3}, {%4,%5,%6,%7}, {%8,%9}, {%0,%1,%2,%3};"
        : "+f"(c0), "+f"(c1), "+f"(c2), "+f"(c3)
        : "r"(a0), "r"(a1), "r"(a2), "r"(a3), "r"(b0), "r"(b1));
}

// ---------------- tf32 tensor-core GEMM (128x128x16 tile, 8 warps) ------------
// C[z] = alpha * A[z] (x) B[z] + bias.  A: MxK row-major.
// B: KxN row-major if !TRANS_B, else NxK row-major (C = A*B^T).
// REQUIRES M%128==0, N%128==0, K%16==0.
#define AS_STRIDE 20
#define BS_STRIDE_NT 132

template <bool TRANS_B>
__global__ void __launch_bounds__(256)
gemm_tc(const float* __restrict__ A, const float* __restrict__ Bm,
        const float* __restrict__ bias, float* __restrict__ C,
        int M, int N, int K, float alpha,
        ll saO, ll saI, int innerCnt,
        ll sbO, ll sbI, ll sC)
{
    const int z = blockIdx.z;
    const float* Ab = A + (ll)(z / innerCnt) * saO + (ll)(z % innerCnt) * saI;
    const float* Bb = Bm + (ll)(z / innerCnt) * sbO + (ll)(z % innerCnt) * sbI;
    float* Cb = C + (ll)z * sC;

    __shared__ float As[128 * AS_STRIDE];                  // [m][k] stride 20
    __shared__ float Bs[128 * AS_STRIDE > 16 * BS_STRIDE_NT ? 128 * AS_STRIDE : 16 * BS_STRIDE_NT];

    const int tid = threadIdx.x;
    const int lane = tid & 31;
    const int warp = tid >> 5;
    const int warpM = warp & 3;          // 4 warp rows  (32 rows each)
    const int warpN = warp >> 2;         // 2 warp cols  (64 cols each)
    const int g  = lane >> 2;            // fragment group row 0..7
    const int tg = lane & 3;             // fragment k/col 0..3

    const int rowBase = blockIdx.y * 128;
    const int colBase = blockIdx.x * 128;

    float acc[2][8][4];
#pragma unroll
    for (int mt = 0; mt < 2; mt++)
#pragma unroll
        for (int nt = 0; nt < 8; nt++)
#pragma unroll
            for (int c = 0; c < 4; c++) acc[mt][nt][c] = 0.f;

    // global-load index precompute (2 float4 per thread per tile)
    const int aM0 = tid >> 2, aKq0 = (tid & 3) << 2;               // id = tid
    const int aM1 = (tid + 256) >> 2, aKq1 = ((tid + 256) & 3) << 2;
    // non-trans B: id -> k = id>>5, n4 = (id&31)*4
    const int bK0 = tid >> 5, bN0 = (tid & 31) << 2;
    const int bK1 = (tid + 256) >> 5, bN1 = ((tid + 256) & 31) << 2;

    float4 ra0, ra1, rb0, rb1;

    // prefetch stage 0
    {
        ra0 = *(const float4*)(Ab + (ll)(rowBase + aM0) * K + aKq0);
        ra1 = *(const float4*)(Ab + (ll)(rowBase + aM1) * K + aKq1);
        if (TRANS_B) {
            rb0 = *(const float4*)(Bb + (ll)(colBase + aM0) * K + aKq0);
            rb1 = *(const float4*)(Bb + (ll)(colBase + aM1) * K + aKq1);
        } else {
            rb0 = *(const float4*)(Bb + (ll)bK0 * N + colBase + bN0);
            rb1 = *(const float4*)(Bb + (ll)bK1 * N + colBase + bN1);
        }
    }

    const int nStages = K >> 4;
    for (int s = 0; s < nStages; s++) {
        // convert + store current stage
        {
            float4 t;
            t.x = f2tf32(ra0.x); t.y = f2tf32(ra0.y); t.z = f2tf32(ra0.z); t.w = f2tf32(ra0.w);
            *(float4*)(As + aM0 * AS_STRIDE + aKq0) = t;
            t.x = f2tf32(ra1.x); t.y = f2tf32(ra1.y); t.z = f2tf32(ra1.z); t.w = f2tf32(ra1.w);
            *(float4*)(As + aM1 * AS_STRIDE + aKq1) = t;
            if (TRANS_B) {
                t.x = f2tf32(rb0.x); t.y = f2tf32(rb0.y); t.z = f2tf32(rb0.z); t.w = f2tf32(rb0.w);
                *(float4*)(Bs + aM0 * AS_STRIDE + aKq0) = t;
                t.x = f2tf32(rb1.x); t.y = f2tf32(rb1.y); t.z = f2tf32(rb1.z); t.w = f2tf32(rb1.w);
                *(float4*)(Bs + aM1 * AS_STRIDE + aKq1) = t;
            } else {
                t.x = f2tf32(rb0.x); t.y = f2tf32(rb0.y); t.z = f2tf32(rb0.z); t.w = f2tf32(rb0.w);
                *(float4*)(Bs + bK0 * BS_STRIDE_NT + bN0) = t;
                t.x = f2tf32(rb1.x); t.y = f2tf32(rb1.y); t.z = f2tf32(rb1.z); t.w = f2tf32(rb1.w);
                *(float4*)(Bs + bK1 * BS_STRIDE_NT + bN1) = t;
            }
        }
        __syncthreads();

        // prefetch next stage into registers
        if (s + 1 < nStages) {
            const int k0 = (s + 1) << 4;
            ra0 = *(const float4*)(Ab + (ll)(rowBase + aM0) * K + k0 + aKq0);
            ra1 = *(const float4*)(Ab + (ll)(rowBase + aM1) * K + k0 + aKq1);
            if (TRANS_B) {
                rb0 = *(const float4*)(Bb + (ll)(colBase + aM0) * K + k0 + aKq0);
                rb1 = *(const float4*)(Bb + (ll)(colBase + aM1) * K + k0 + aKq1);
            } else {
                rb0 = *(const float4*)(Bb + (ll)(k0 + bK0) * N + colBase + bN0);
                rb1 = *(const float4*)(Bb + (ll)(k0 + bK1) * N + colBase + bN1);
            }
        }

        // compute from smem: two k8 sub-steps
#pragma unroll
        for (int ks = 0; ks < 16; ks += 8) {
            uint32_t afr[2][4];
#pragma unroll
            for (int mt = 0; mt < 2; mt++) {
                const int r = warpM * 32 + mt * 16;
                afr[mt][0] = __float_as_uint(As[(r + g)     * AS_STRIDE + ks + tg]);
                afr[mt][1] = __float_as_uint(As[(r + g + 8) * AS_STRIDE + ks + tg]);
                afr[mt][2] = __float_as_uint(As[(r + g)     * AS_STRIDE + ks + tg + 4]);
                afr[mt][3] = __float_as_uint(As[(r + g + 8) * AS_STRIDE + ks + tg + 4]);
            }
            uint32_t bfr[8][2];
#pragma unroll
            for (int nt = 0; nt < 8; nt++) {
                const int c = warpN * 64 + nt * 8;
                if (TRANS_B) {
                    bfr[nt][0] = __float_as_uint(Bs[(c + g) * AS_STRIDE + ks + tg]);
                    bfr[nt][1] = __float_as_uint(Bs[(c + g) * AS_STRIDE + ks + tg + 4]);
                } else {
                    bfr[nt][0] = __float_as_uint(Bs[(ks + tg)     * BS_STRIDE_NT + c + g]);
                    bfr[nt][1] = __float_as_uint(Bs[(ks + tg + 4) * BS_STRIDE_NT + c + g]);
                }
            }
#pragma unroll
            for (int mt = 0; mt < 2; mt++)
#pragma unroll
                for (int nt = 0; nt < 8; nt++)
                    mma_tf32(acc[mt][nt][0], acc[mt][nt][1], acc[mt][nt][2], acc[mt][nt][3],
                             afr[mt][0], afr[mt][1], afr[mt][2], afr[mt][3],
                             bfr[nt][0], bfr[nt][1]);
        }
        __syncthreads();
    }

    // epilogue
#pragma unroll
    for (int mt = 0; mt < 2; mt++) {
        const int r0 = rowBase + warpM * 32 + mt * 16 + g;
#pragma unroll
        for (int nt = 0; nt < 8; nt++) {
            const int col = colBase + warpN * 64 + nt * 8 + tg * 2;
            float2 bv = make_float2(0.f, 0.f);
            if (bias) bv = *(const float2*)&bias[col];
            float2 o;
            o.x = alpha * acc[mt][nt][0] + bv.x;
            o.y = alpha * acc[mt][nt][1] + bv.y;
            *(float2*)(Cb + (ll)r0 * N + col) = o;
            o.x = alpha * acc[mt][nt][2] + bv.x;
            o.y = alpha * acc[mt][nt][3] + bv.y;
            *(float2*)(Cb + (ll)(r0 + 8) * N + col) = o;
        }
    }
}

// ---------------- gates + selection scores ------------------------------------
__global__ void gates_scores_kernel(const float* __restrict__ x,
                                    const float* __restrict__ Wg, const float* __restrict__ bg,
                                    const float* __restrict__ Ws, const float* __restrict__ bs,
                                    float* __restrict__ gates, float* __restrict__ scores)
{
    const int row = blockIdx.x * (blockDim.x >> 5) + (threadIdx.x >> 5);
    const int lane = threadIdx.x & 31;
    if (row >= B_ * L_) return;
    const float* xr = x + (ll)row * H_;
    float a0 = 0.f, a1 = 0.f, a2 = 0.f, a3 = 0.f;
    for (int k = lane; k < H_; k += 32) {
        const float xv = xr[k];
        a0 += xv * Wg[k * 3 + 0];
        a1 += xv * Wg[k * 3 + 1];
        a2 += xv * Wg[k * 3 + 2];
        a3 += xv * Ws[k];
    }
#pragma unroll
    for (int o = 16; o > 0; o >>= 1) {
        a0 += __shfl_down_sync(0xffffffffu, a0, o);
        a1 += __shfl_down_sync(0xffffffffu, a1, o);
        a2 += __shfl_down_sync(0xffffffffu, a2, o);
        a3 += __shfl_down_sync(0xffffffffu, a3, o);
    }
    if (lane == 0) {
        float s0 = 1.f / (1.f + expf(-(a0 + bg[0])));
        float s1 = 1.f / (1.f + expf(-(a1 + bg[1])));
        float s2 = 1.f / (1.f + expf(-(a2 + bg[2])));
        float inv = 1.f / (s0 + s1 + s2 + 1e-6f);
        gates[row * 3 + 0] = s0 * inv;
        gates[row * 3 + 1] = s1 * inv;
        gates[row * 3 + 2] = s2 * inv;
        scores[row] = a3 + bs[0];
    }
}

// ---------------- top-512 per batch ------------------------------------------
__global__ void topk_kernel(const float* __restrict__ scores, int* __restrict__ idx_out)
{
    __shared__ float sv[L_];
    __shared__ int   si[L_];
    __shared__ int   top[KSEL_];
    const int b = blockIdx.x;
    const float* s = scores + (ll)b * L_;
    for (int i = threadIdx.x; i < L_; i += blockDim.x) { sv[i] = s[i]; si[i] = i; }
    __syncthreads();
    for (int k = 2; k <= L_; k <<= 1)
        for (int j = k >> 1; j > 0; j >>= 1) {
            for (int i = threadIdx.x; i < L_; i += blockDim.x) {
                const int ixj = i ^ j;
                if (ixj > i) {
                    const bool desc = ((i & k) == 0);
                    const float a = sv[i], c = sv[ixj];
                    const bool sw = desc ? (a < c) : (a > c);
                    if (sw) {
                        sv[i] = c; sv[ixj] = a;
                        const int t = si[i]; si[i] = si[ixj]; si[ixj] = t;
                    }
                }
            }
            __syncthreads();
        }
    for (int i = threadIdx.x; i < KSEL_; i += blockDim.x) top[i] = si[i];
    __syncthreads();
    for (int k = 2; k <= KSEL_; k <<= 1)
        for (int j = k >> 1; j > 0; j >>= 1) {
            for (int i = threadIdx.x; i < KSEL_; i += blockDim.x) {
                const int ixj = i ^ j;
                if (ixj > i) {
                    const bool asc = ((i & k) == 0);
                    const int a = top[i], c = top[ixj];
                    const bool sw = asc ? (a > c) : (a < c);
                    if (sw) { top[i] = c; top[ixj] = a; }
                }
            }
            __syncthreads();
        }
    for (int i = threadIdx.x; i < KSEL_; i += blockDim.x) idx_out[b * KSEL_ + i] = top[i];
}

// ---------------- gather selected rows ----------------------------------------
__global__ void gather_kernel(const float* __restrict__ Q, const float* __restrict__ K,
                              const float* __restrict__ V, const int* __restrict__ idx,
                              float* __restrict__ Qs, float* __restrict__ Ks, float* __restrict__ Vs)
{
    const int b = blockIdx.y, r = blockIdx.x;
    const int src = idx[b * KSEL_ + r];
    const ll so = ((ll)b * L_ + src) * H_;
    const ll dst = ((ll)b * KSEL_ + r) * H_;
    for (int i = threadIdx.x; i < H_; i += blockDim.x) {
        Qs[dst + i] = Q[so + i];
        Ks[dst + i] = K[so + i];
        Vs[dst + i] = V[so + i];
    }
}

// ---------------- row softmax --------------------------------------------------
__global__ void softmax_kernel(float* __restrict__ S, int n)
{
    const ll row = blockIdx.x;
    float* s = S + row * (ll)n;
    const int tid = threadIdx.x;
    __shared__ float red[32];
    __shared__ float bc;

    float m = -1e30f;
    for (int i = tid; i < n; i += blockDim.x) m = fmaxf(m, s[i]);
#pragma unroll
    for (int o = 16; o > 0; o >>= 1) m = fmaxf(m, __shfl_xor_sync(0xffffffffu, m, o));
    if ((tid & 31) == 0) red[tid >> 5] = m;
    __syncthreads();
    if (tid == 0) {
        float mm = -1e30f;
        for (int i = 0; i < (int)(blockDim.x >> 5); i++) mm = fmaxf(mm, red[i]);
        bc = mm;
    }
    __syncthreads();
    m = bc;
    __syncthreads();

    float sum = 0.f;
    for (int i = tid; i < n; i += blockDim.x) {
        const float e = expf(s[i] - m);
        s[i] = e;
        sum += e;
    }
#pragma unroll
    for (int o = 16; o > 0; o >>= 1) sum += __shfl_xor_sync(0xffffffffu, sum, o);
    if ((tid & 31) == 0) red[tid >> 5] = sum;
    __syncthreads();
    if (tid == 0) {
        float ss = 0.f;
        for (int i = 0; i < (int)(blockDim.x >> 5); i++) ss += red[i];
        bc = 1.f / ss;
    }
    __syncthreads();
    const float inv = bc;
    for (int i = tid; i < n; i += blockDim.x) s[i] *= inv;
}

// ---------------- assemble gated combined -------------------------------------
__global__ void assemble_kernel(const float* __restrict__ comp_out, const float* __restrict__ sel_out,
                                const float* __restrict__ win_out, const float* __restrict__ gates,
                                float* __restrict__ comb)
{
    const ll t = blockIdx.x;
    const int b = (int)(t >> 12), l = (int)(t & 4095);
    const float g0 = gates[t * 3 + 0], g1 = gates[t * 3 + 1], g2 = gates[t * 3 + 2];
    float* c = comb + t * (ll)(3 * H_);
    const float* co = comp_out + ((ll)b * LC_ + l) * H_;
    const float* so = sel_out + ((ll)b * KSEL_ + l) * H_;
    const float* wo = win_out + t * (ll)H_;
    const bool hasC = (l < LC_), hasS = (l < KSEL_);
    for (int i = threadIdx.x; i < H_; i += blockDim.x) {
        c[i]          = hasC ? co[i] * g0 : 0.f;
        c[H_ + i]     = hasS ? so[i] * g1 : 0.f;
        c[2 * H_ + i] = wo[i] * g2;
    }
}

// ---------------- residual + layernorm ----------------------------------------
__global__ void final_ln_kernel(const float* __restrict__ pre, const float* __restrict__ x,
                                float* __restrict__ out)
{
    const ll row = blockIdx.x;
    const float* p = pre + row * (ll)H_;
    const float* xr = x + row * (ll)H_;
    float* o = out + row * (ll)H_;
    const int tid = threadIdx.x;
    __shared__ float buf[H_];
    __shared__ float red[64];
    __shared__ float stats[2];

    float s = 0.f, ss = 0.f;
    for (int i = tid; i < H_; i += blockDim.x) {
        const float v = 0.5f * (p[i] + xr[i]);
        buf[i] = v;
        s += v;
        ss += v * v;
    }
#pragma unroll
    for (int o2 = 16; o2 > 0; o2 >>= 1) {
        s  += __shfl_xor_sync(0xffffffffu, s, o2);
        ss += __shfl_xor_sync(0xffffffffu, ss, o2);
    }
    if ((tid & 31) == 0) { red[tid >> 5] = s; red[32 + (tid >> 5)] = ss; }
    __syncthreads();
    if (tid == 0) {
        float ts = 0.f, tss = 0.f;
        for (int i = 0; i < (int)(blockDim.x >> 5); i++) { ts += red[i]; tss += red[32 + i]; }
        const float mean = ts / (float)H_;
        const float var = tss / (float)H_ - mean * mean;
        stats[0] = mean;
        stats[1] = rsqrtf(var + 1e-6f);
    }
    __syncthreads();
    const float mean = stats[0], inv = stats[1];
    for (int i = tid; i < H_; i += blockDim.x) o[i] = (buf[i] - mean) * inv;
}

// ------------------------------- launcher --------------------------------------
extern "C" void kernel_launch(void* const* d_in, const int* in_sizes, int n_in,
                              void* d_out, int out_size)
{
    const float* x  = (const float*)d_in[0];
    const float* Wq = (const float*)d_in[1];
    const float* bq = (const float*)d_in[2];
    const float* Wk = (const float*)d_in[3];
    const float* bk = (const float*)d_in[4];
    const float* Wv = (const float*)d_in[5];
    const float* bv = (const float*)d_in[6];
    const float* Wo = (const float*)d_in[7];
    const float* bo = (const float*)d_in[8];
    const float* Wg = (const float*)d_in[9];
    const float* bg = (const float*)d_in[10];
    const float* Wc = (const float*)d_in[11];
    const float* bc = (const float*)d_in[12];
    const float* Ws = (const float*)d_in[13];
    const float* bs = (const float*)d_in[14];
    float* out = (float*)d_out;

    float *Q, *K, *V, *cmp, *Qc, *Kc, *Vc, *S, *comp_out;
    float *Qs, *Ks, *Vs, *sel_out, *win_out, *comb, *pre, *gates, *scores;
    int* idx;
    cudaGetSymbolAddress((void**)&Q, g_Q);
    cudaGetSymbolAddress((void**)&K, g_Kbuf);
    cudaGetSymbolAddress((void**)&V, g_Vbuf);
    cudaGetSymbolAddress((void**)&cmp, g_cmp);
    cudaGetSymbolAddress((void**)&Qc, g_Qc);
    cudaGetSymbolAddress((void**)&Kc, g_Kc);
    cudaGetSymbolAddress((void**)&Vc, g_Vc);
    cudaGetSymbolAddress((void**)&S, g_S);
    cudaGetSymbolAddress((void**)&comp_out, g_comp_out);
    cudaGetSymbolAddress((void**)&Qs, g_Qs);
    cudaGetSymbolAddress((void**)&Ks, g_Ks);
    cudaGetSymbolAddress((void**)&Vs, g_Vs);
    cudaGetSymbolAddress((void**)&sel_out, g_sel_out);
    cudaGetSymbolAddress((void**)&win_out, g_win_out);
    cudaGetSymbolAddress((void**)&comb, g_comb);
    cudaGetSymbolAddress((void**)&pre, g_pre);
    cudaGetSymbolAddress((void**)&gates, g_gates);
    cudaGetSymbolAddress((void**)&scores, g_scores);
    cudaGetSymbolAddress((void**)&idx, g_idx);

    const int MT = B_ * L_;

    gates_scores_kernel<<<MT / 8, 256>>>(x, Wg, bg, Ws, bs, gates, scores);

    {
        dim3 g(H_ / 128, MT / 128, 1);
        gemm_tc<false><<<g, 256>>>(x, Wq, bq, Q, MT, H_, H_, 1.f, 0, 0, 1, 0, 0, 0);
        gemm_tc<false><<<g, 256>>>(x, Wk, bk, K, MT, H_, H_, 1.f, 0, 0, 1, 0, 0, 0);
        gemm_tc<false><<<g, 256>>>(x, Wv, bv, V, MT, H_, H_, 1.f, 0, 0, 1, 0, 0, 0);
    }

    {
        dim3 g(H_ / 128, (B_ * LC_) / 128, 1);
        gemm_tc<false><<<g, 256>>>(x, Wc, bc, cmp, B_ * LC_, H_, 4 * H_, 1.f, 0, 0, 1, 0, 0, 0);
        gemm_tc<false><<<g, 256>>>(cmp, Wq, bq, Qc, B_ * LC_, H_, H_, 1.f, 0, 0, 1, 0, 0, 0);
        gemm_tc<false><<<g, 256>>>(cmp, Wk, bk, Kc, B_ * LC_, H_, H_, 1.f, 0, 0, 1, 0, 0, 0);
        gemm_tc<false><<<g, 256>>>(cmp, Wv, bv, Vc, B_ * LC_, H_, H_, 1.f, 0, 0, 1, 0, 0, 0);
    }

    topk_kernel<<<B_, 512>>>(scores, idx);
    gather_kernel<<<dim3(KSEL_, B_), 256>>>(Q, K, V, idx, Qs, Ks, Vs);

    // compressed attention
    gemm_tc<true><<<dim3(LC_ / 128, LC_ / 128, B_), 256>>>(
        Qc, Kc, nullptr, S, LC_, LC_, H_, SCALE_,
        (ll)LC_ * H_, 0, 1, (ll)LC_ * H_, 0, (ll)LC_ * LC_);
    softmax_kernel<<<B_ * LC_, 256>>>(S, LC_);
    gemm_tc<false><<<dim3(H_ / 128, LC_ / 128, B_), 256>>>(
        S, Vc, nullptr, comp_out, LC_, H_, LC_, 1.f,
        (ll)LC_ * LC_, 0, 1, (ll)LC_ * H_, 0, (ll)LC_ * H_);

    // selected attention
    gemm_tc<true><<<dim3(KSEL_ / 128, KSEL_ / 128, B_), 256>>>(
        Qs, Ks, nullptr, S, KSEL_, KSEL_, H_, SCALE_,
        (ll)KSEL_ * H_, 0, 1, (ll)KSEL_ * H_, 0, (ll)KSEL_ * KSEL_);
    softmax_kernel<<<B_ * KSEL_, 256>>>(S, KSEL_);
    gemm_tc<false><<<dim3(H_ / 128, KSEL_ / 128, B_), 256>>>(
        S, Vs, nullptr, sel_out, KSEL_, H_, KSEL_, 1.f,
        (ll)KSEL_ * KSEL_, 0, 1, (ll)KSEL_ * H_, 0, (ll)KSEL_ * H_);

    // window attention
    gemm_tc<true><<<dim3(WIN_ / 128, WIN_ / 128, B_ * NW_), 256>>>(
        Q, K, nullptr, S, WIN_, WIN_, H_, SCALE_,
        (ll)L_ * H_, (ll)128 * H_, NW_,
        (ll)L_ * H_, (ll)128 * H_, (ll)WIN_ * WIN_);
    softmax_kernel<<<B_ * NW_ * WIN_, 256>>>(S, WIN_);
    gemm_tc<false><<<dim3(H_ / 128, WIN_ / 128, B_ * NW_), 256>>>(
        S, V, nullptr, win_out, WIN_, H_, WIN_, 1.f,
        (ll)NW_ * WIN_ * WIN_, (ll)WIN_ * WIN_, NW_,
        (ll)L_ * H_, (ll)128 * H_, (ll)WIN_ * H_);

    assemble_kernel<<<MT, 256>>>(comp_out, sel_out, win_out, gates, comb);
    gemm_tc<false><<<dim3(H_ / 128, MT / 128, 1), 256>>>(
        comb, Wo, bo, pre, MT, H_, 3 * H_, 1.f, 0, 0, 1, 0, 0, 0);
    final_ln_kernel<<<MT, 256>>>(pre, x, out);
}